// round 1
// baseline (speedup 1.0000x reference)
#include <cuda_runtime.h>
#include <cuda_bf16.h>
#include <cstdint>
#include <math.h>

#define NQ    2048
#define DIM   256
#define NF    100000
#define NCLS  1000
#define KSEL  16
#define TAUF  0.2f
#define LSCALE 20.0f

#define BM 128
#define BN 128
#define BK 64
#define NSTRIPE 26
#define TPS 31              // tiles per stripe
#define PS (TPS*BN)         // 3968 columns per stripe
#define KP 16               // per-stripe per-row candidates kept
#define NCAND (NSTRIPE*KP)  // 416 candidates per row
#define CSEL 32             // candidates rescored exactly

#define SMEM_A   (BM*DIM*2)          // 65536
#define SMEM_B   (2*BN*BK*2)         // 32768
#define SMEM_S   (BM*129*4)          // 66048
#define SMEM_TOTAL (SMEM_A + SMEM_B + SMEM_S)  // 164352

// ---------------- device scratch (static allocation is allowed) ----------------
__device__ __nv_bfloat16 g_xb[NQ*DIM];
__device__ float         g_xn[NQ*DIM];
__device__ __nv_bfloat16 g_mb[(size_t)NF*DIM];
__device__ float         g_cval[(size_t)NQ*NCAND];
__device__ int           g_cidx[(size_t)NQ*NCAND];

// ---------------- small PTX helpers ----------------
__device__ __forceinline__ void cpa16(unsigned dst, const void* src, int sz){
  asm volatile("cp.async.cg.shared.global [%0], [%1], 16, %2;\n"
    :: "r"(dst), "l"(__cvta_generic_to_global(src)), "r"(sz));
}
__device__ __forceinline__ void cpa_commit(){ asm volatile("cp.async.commit_group;\n"); }
template<int N> __device__ __forceinline__ void cpa_wait(){
  asm volatile("cp.async.wait_group %0;\n" :: "n"(N));
}
__device__ __forceinline__ void ldsm4(uint32_t* r, unsigned addr){
  asm volatile("ldmatrix.sync.aligned.m8n8.x4.shared.b16 {%0,%1,%2,%3}, [%4];\n"
    : "=r"(r[0]), "=r"(r[1]), "=r"(r[2]), "=r"(r[3]) : "r"(addr));
}
__device__ __forceinline__ void mma16816(float* d, const uint32_t* a, uint32_t b0, uint32_t b1){
  asm volatile(
    "mma.sync.aligned.m16n8k16.row.col.f32.bf16.bf16.f32 "
    "{%0,%1,%2,%3}, {%4,%5,%6,%7}, {%8,%9}, {%0,%1,%2,%3};\n"
    : "+f"(d[0]), "+f"(d[1]), "+f"(d[2]), "+f"(d[3])
    : "r"(a[0]), "r"(a[1]), "r"(a[2]), "r"(a[3]), "r"(b0), "r"(b1));
}

// ---------------- kernel 1: standardize + L2 normalize x ----------------
__global__ void prep_kernel(const float* __restrict__ x, const float* __restrict__ mean,
                            const float* __restrict__ stdv){
  int r = blockIdx.x, t = threadIdx.x;
  float v = (x[r*DIM + t] - mean[t]) / stdv[t];
  float s = v*v;
  #pragma unroll
  for (int o = 16; o; o >>= 1) s += __shfl_xor_sync(0xffffffffu, s, o);
  __shared__ float ws[8];
  __shared__ float nrm;
  if ((t & 31) == 0) ws[t >> 5] = s;
  __syncthreads();
  if (t == 0){
    float tot = 0.f;
    #pragma unroll
    for (int i = 0; i < 8; i++) tot += ws[i];
    nrm = fmaxf(sqrtf(tot), 1e-6f);
  }
  __syncthreads();
  float o = v / nrm;
  g_xn[r*DIM + t] = o;
  g_xb[r*DIM + t] = __float2bfloat16(o);
}

// ---------------- kernel 2: fp32 -> bf16 convert of mem_features ----------------
__global__ void conv_kernel(const float* __restrict__ mf){
  int stride = gridDim.x * blockDim.x;
  int n4 = NF*DIM/4;
  for (int i = blockIdx.x*blockDim.x + threadIdx.x; i < n4; i += stride){
    float4 f = ((const float4*)mf)[i];
    __nv_bfloat162* o = (__nv_bfloat162*)g_mb;
    o[2*i]   = __floats2bfloat162_rn(f.x, f.y);
    o[2*i+1] = __floats2bfloat162_rn(f.z, f.w);
  }
}

// ---------------- kernel 3: fused bf16 GEMM + streaming per-stripe top-KP ----------------
__device__ __forceinline__ void load_b_tile(unsigned sB_u, int buf, int kc, int nb, int t){
  unsigned bbase = sB_u + (unsigned)buf * (unsigned)(BN*BK*2);
  #pragma unroll
  for (int i = 0; i < 4; i++){
    int id = t + 256*i;
    int r = id >> 3, c = id & 7;
    int nrow = nb + r;
    const char* src = (const char*)g_mb +
        ((size_t)(nrow < NF ? nrow : 0) * DIM + kc*64 + c*8) * 2;
    unsigned dst = bbase + (unsigned)((r*8 + ((c ^ r) & 7)) * 16);
    cpa16(dst, src, (nrow < NF) ? 16 : 0);
  }
  cpa_commit();
}

__global__ void __launch_bounds__(256, 1) gemm_topk_kernel(){
  extern __shared__ char smem[];
  char*  sBc = smem + SMEM_A;
  float* sS  = (float*)(smem + SMEM_A + SMEM_B);
  const unsigned sA_u = (unsigned)__cvta_generic_to_shared(smem);
  const unsigned sB_u = (unsigned)__cvta_generic_to_shared(sBc);

  int t = threadIdx.x, lane = t & 31, w = t >> 5;
  int m0 = blockIdx.x * BM;
  int sbase = blockIdx.y * PS;
  int rem = NF - sbase;
  int ntiles = (rem >= PS) ? TPS : ((rem + BN - 1) / BN);

  // ---- load A tile [128 x 256] bf16 once (swizzled for ldmatrix) ----
  #pragma unroll
  for (int i = 0; i < 16; i++){
    int id = t + 256*i;
    int row = id >> 5, c = id & 31;
    const char* src = (const char*)g_xb + ((size_t)(m0 + row)*DIM + c*8) * 2;
    int phys = (c & 24) | ((c ^ row) & 7);
    cpa16(sA_u + (unsigned)((row*32 + phys)*16), src, 16);
  }
  cpa_commit();
  cpa_wait<0>();
  __syncthreads();

  // ---- per-row top-KP state (threads 0..127 own row t) ----
  float tv[KP]; int ti[KP];
  #pragma unroll
  for (int i = 0; i < KP; i++){ tv[i] = -INFINITY; ti[i] = 0; }
  float tmin = -INFINITY; int minpos = 0;

  int wr = (w >> 2) * 64;   // warp row base within tile
  int wc = (w & 3) * 32;    // warp col base within tile

  for (int nt = 0; nt < ntiles; nt++){
    int nb = sbase + nt * BN;
    float acc[4][4][4];
    #pragma unroll
    for (int mf = 0; mf < 4; mf++)
      #pragma unroll
      for (int nf = 0; nf < 4; nf++)
        #pragma unroll
        for (int q = 0; q < 4; q++) acc[mf][nf][q] = 0.f;

    int buf = 0;
    load_b_tile(sB_u, 0, 0, nb, t);
    #pragma unroll
    for (int kc = 0; kc < 4; kc++){
      if (kc < 3) load_b_tile(sB_u, buf ^ 1, kc + 1, nb, t);
      if (kc < 3) cpa_wait<1>(); else cpa_wait<0>();
      __syncthreads();
      unsigned bbase = sB_u + (unsigned)buf * (unsigned)(BN*BK*2);
      #pragma unroll
      for (int s = 0; s < 4; s++){
        int c0 = kc*8 + 2*s;
        uint32_t af[4][4];
        #pragma unroll
        for (int mf = 0; mf < 4; mf++){
          int row = wr + 16*mf + (lane & 15);
          int c = c0 + (lane >> 4);
          int phys = (c & 24) | ((c ^ row) & 7);
          ldsm4(af[mf], sA_u + (unsigned)((row*32 + phys)*16));
        }
        uint32_t b0v[4], b1v[4];
        #pragma unroll
        for (int p = 0; p < 2; p++){
          int row = wc + 16*p + (lane & 15);
          int c = 2*s + (lane >> 4);
          int phys = (c ^ row) & 7;
          uint32_t r[4];
          ldsm4(r, bbase + (unsigned)((row*8 + phys)*16));
          b0v[2*p] = r[0]; b0v[2*p+1] = r[1]; b1v[2*p] = r[2]; b1v[2*p+1] = r[3];
        }
        #pragma unroll
        for (int mf = 0; mf < 4; mf++)
          #pragma unroll
          for (int nf = 0; nf < 4; nf++)
            mma16816(acc[mf][nf], af[mf], b0v[nf], b1v[nf]);
      }
      __syncthreads();
      buf ^= 1;
    }

    // ---- dump sims tile to smem, then streaming top-k scan ----
    int r0r = wr + (lane >> 2);
    int c0c = wc + 2*(lane & 3);
    #pragma unroll
    for (int mf = 0; mf < 4; mf++){
      #pragma unroll
      for (int nf = 0; nf < 4; nf++){
        int rr = r0r + 16*mf, cc = c0c + 8*nf;
        sS[rr*129 + cc]       = acc[mf][nf][0];
        sS[rr*129 + cc + 1]   = acc[mf][nf][1];
        sS[(rr+8)*129 + cc]   = acc[mf][nf][2];
        sS[(rr+8)*129 + cc+1] = acc[mf][nf][3];
      }
    }
    __syncthreads();
    if (t < BM){
      for (int j = 0; j < BN; j++){
        float v = sS[t*129 + j];
        int gc = nb + j;
        if (v > tmin && gc < NF){
          #pragma unroll
          for (int i = 0; i < KP; i++) if (i == minpos){ tv[i] = v; ti[i] = gc; }
          tmin = tv[0]; minpos = 0;
          #pragma unroll
          for (int i = 1; i < KP; i++) if (tv[i] < tmin){ tmin = tv[i]; minpos = i; }
        }
      }
    }
    __syncthreads();
  }

  if (t < BM){
    size_t base = (size_t)(m0 + t) * NCAND + (size_t)blockIdx.y * KP;
    #pragma unroll
    for (int i = 0; i < KP; i++){ g_cval[base + i] = tv[i]; g_cidx[base + i] = ti[i]; }
  }
}

// ---------------- kernel 4: merge candidates, exact rescore, softmax, scatter ----------------
__global__ void __launch_bounds__(128) merge_kernel(const float* __restrict__ mf,
                                                    const int* __restrict__ lab,
                                                    float* __restrict__ out){
  int row = blockIdx.x, t = threadIdx.x, lane = t & 31, w = t >> 5;
  __shared__ float cv[NCAND];
  __shared__ int   ci[NCAND];
  __shared__ float xs[DIM];
  __shared__ float accs[NCLS];
  __shared__ int   selIdx[CSEL];
  __shared__ float ex[CSEL];
  __shared__ float swv[4]; __shared__ int swp[4];
  __shared__ float wgt[KSEL]; __shared__ int flab[KSEL];

  for (int j = t; j < NCAND; j += 128){
    cv[j] = g_cval[(size_t)row*NCAND + j];
    ci[j] = g_cidx[(size_t)row*NCAND + j];
  }
  for (int j = t; j < DIM; j += 128) xs[j] = g_xn[row*DIM + j];
  __syncthreads();

  // top-CSEL by bf16 sims (candidate indices are unique by construction)
  for (int it = 0; it < CSEL; it++){
    float bv = -INFINITY; int bp = 0;
    for (int j = t; j < NCAND; j += 128){ if (cv[j] > bv){ bv = cv[j]; bp = j; } }
    #pragma unroll
    for (int o = 16; o; o >>= 1){
      float ov = __shfl_down_sync(0xffffffffu, bv, o);
      int   op = __shfl_down_sync(0xffffffffu, bp, o);
      if (ov > bv){ bv = ov; bp = op; }
    }
    if (lane == 0){ swv[w] = bv; swp[w] = bp; }
    __syncthreads();
    if (t == 0){
      float best = swv[0]; int bsp = swp[0];
      for (int q = 1; q < 4; q++) if (swv[q] > best){ best = swv[q]; bsp = swp[q]; }
      selIdx[it] = ci[bsp];
      cv[bsp] = -INFINITY;
    }
    __syncthreads();
  }

  // exact fp32 rescore of the CSEL candidates (warp per candidate)
  for (int rr = 0; rr < CSEL/4; rr++){
    int c = rr*4 + w;
    const float* fr = mf + (size_t)selIdx[c] * DIM;
    float s = 0.f;
    #pragma unroll
    for (int j = 0; j < 8; j++){ int k = lane + 32*j; s += fr[k] * xs[k]; }
    #pragma unroll
    for (int o = 16; o; o >>= 1) s += __shfl_down_sync(0xffffffffu, s, o);
    if (lane == 0) ex[c] = s;
  }
  __syncthreads();

  if (t == 0){
    unsigned um = 0;
    float sval[KSEL]; int sfeat[KSEL];
    for (int it = 0; it < KSEL; it++){
      float bv = -INFINITY; int bc = 0;
      for (int c = 0; c < CSEL; c++){
        if (!((um >> c) & 1u) && ex[c] > bv){ bv = ex[c]; bc = c; }
      }
      um |= 1u << bc;
      sval[it] = bv; sfeat[it] = selIdx[bc];
    }
    float m = sval[0], sum = 0.f;
    for (int i = 0; i < KSEL; i++){ float e = expf((sval[i]-m)/TAUF); wgt[i] = e; sum += e; }
    float inv = 1.f / sum;
    for (int i = 0; i < KSEL; i++){ wgt[i] *= inv; flab[i] = lab[sfeat[i]]; }
  }
  for (int c = t; c < NCLS; c += 128) accs[c] = 0.f;
  __syncthreads();
  if (t == 0){
    for (int i = 0; i < KSEL; i++) accs[flab[i]] += wgt[i];
  }
  __syncthreads();
  for (int c = t; c < NCLS; c += 128) out[(size_t)row*NCLS + c] = accs[c] * LSCALE;
}

// ---------------- launch ----------------
extern "C" void kernel_launch(void* const* d_in, const int* in_sizes, int n_in,
                              void* d_out, int out_size){
  const float* x    = (const float*)d_in[0];
  const float* mean = (const float*)d_in[1];
  const float* stdv = (const float*)d_in[2];
  const float* mf   = (const float*)d_in[3];
  const int*   lab  = (const int*)d_in[4];
  float* out = (float*)d_out;

  cudaFuncSetAttribute(gemm_topk_kernel, cudaFuncAttributeMaxDynamicSharedMemorySize, SMEM_TOTAL);

  prep_kernel<<<NQ, DIM>>>(x, mean, stdv);
  conv_kernel<<<2048, 256>>>(mf);
  gemm_topk_kernel<<<dim3(NQ/BM, NSTRIPE), 256, SMEM_TOTAL>>>();
  merge_kernel<<<NQ, 128>>>(mf, lab, out);
}